// round 10
// baseline (speedup 1.0000x reference)
#include <cuda_runtime.h>

#define BATCH 32
#define IN_H  128
#define IN_W  512
#define CHAN  32
#define OUT_H 64
#define OUT_W 256

// Warp-per-point gather scheme.
// Block = 256 threads = 8 warps, covers 64 consecutive wx for one (b, hy).
// Phase 1: threads 0..63 compute per-point weights + pixel indices -> smem.
// Phase 2: each warp handles 8 points (2 batches of 4). For each point the
//          32 lanes load one float each of the 4 source pixels (LDG.32,
//          exactly one 128B line per instruction -> no within-LDG replays),
//          blend with broadcast weights, store one line (STG.32).
// Grid = 4 wx-tiles * 64 hy * 32 b = 8192 blocks.

struct PParam {
    float    wA, wB, wC, wD;
    unsigned pA, pB, pC, pD;   // pixel indices (pix = b*H*W + y*W + x)
};

__global__ void __launch_bounds__(256, 6)
stn_bilinear_kernel(const float* __restrict__ image,
                    const float* __restrict__ theta,
                    float* __restrict__ out)
{
    __shared__ PParam sp[64];

    const unsigned tid = threadIdx.x;
    const unsigned bid = blockIdx.x;
    const unsigned wx_base = (bid & 3u) << 6;      // 4 tiles of 64
    const unsigned r       = bid >> 2;
    const unsigned hy      = r & 63u;              // 0..63
    const unsigned b       = r >> 6;               // 0..31

    // ---- Phase 1: 64 threads compute params for the 64 points ----
    if (tid < 64u) {
        const unsigned wx = wx_base + tid;

        const float xg = (float)wx * (2.0f / 255.0f) - 1.0f;
        const float yg = (float)hy * (2.0f / 63.0f) - 1.0f;

        // theta[b] 2x3; reference hack: zero row 1 of batch 0, row 0 of batch 1
        const float* th = theta + b * 6u;
        float t00 = __ldg(th + 0), t01 = __ldg(th + 1), t02 = __ldg(th + 2);
        float t10 = __ldg(th + 3), t11 = __ldg(th + 4), t12 = __ldg(th + 5);
        if (b == 0u) { t10 = 0.0f; t11 = 0.0f; t12 = 0.0f; }
        if (b == 1u) { t00 = 0.0f; t01 = 0.0f; t02 = 0.0f; }

        float cx = t00 * xg + t01 * yg + t02;
        float cy = t10 * xg + t11 * yg + t12;

        float x = 0.5f * (cx + 1.0f) * (float)IN_W;   // uses W, not W-1
        float y = 0.5f * (cy + 1.0f) * (float)IN_H;

        int x0 = (int)x;                              // trunc toward zero
        int y0 = (int)y;
        int x1 = x0 + 1;
        int y1 = y0 + 1;
        x0 = min(max(x0, 0), IN_W - 1);               // clip BEFORE weights
        x1 = min(max(x1, 0), IN_W - 1);
        y0 = min(max(y0, 0), IN_H - 1);
        y1 = min(max(y1, 0), IN_H - 1);

        float x0f = (float)x0, x1f = (float)x1;
        float y0f = (float)y0, y1f = (float)y1;

        PParam pp;
        pp.wA = (x1f - x) * (y1f - y);
        pp.wB = (x1f - x) * (y - y0f);
        pp.wC = (x - x0f) * (y1f - y);
        pp.wD = (x - x0f) * (y - y0f);

        const unsigned basePix = b * (unsigned)(IN_H * IN_W);
        const unsigned row0 = basePix + (unsigned)y0 * (unsigned)IN_W;
        const unsigned row1 = basePix + (unsigned)y1 * (unsigned)IN_W;
        pp.pA = row0 + (unsigned)x0;
        pp.pB = row1 + (unsigned)x0;
        pp.pC = row0 + (unsigned)x1;
        pp.pD = row1 + (unsigned)x1;

        sp[tid] = pp;
    }
    __syncthreads();

    // ---- Phase 2: warp-per-point gathers ----
    const unsigned lane = tid & 31u;
    const unsigned warp = tid >> 5;

    const unsigned oRow = ((b * (unsigned)OUT_H + hy) * (unsigned)OUT_W + wx_base) * 32u + lane;

    #pragma unroll
    for (int batch = 0; batch < 2; ++batch) {
        const unsigned p0 = warp * 8u + (unsigned)batch * 4u;

        // Issue all 16 single-line gathers back-to-back
        float vA[4], vB[4], vC[4], vD[4];
        #pragma unroll
        for (int k = 0; k < 4; ++k) {
            const PParam pp = sp[p0 + k];
            vA[k] = __ldg(image + ((pp.pA << 5) + lane));
            vB[k] = __ldg(image + ((pp.pB << 5) + lane));
            vC[k] = __ldg(image + ((pp.pC << 5) + lane));
            vD[k] = __ldg(image + ((pp.pD << 5) + lane));
        }

        // Blend + store (weights re-read from smem: broadcast LDS, cheap)
        #pragma unroll
        for (int k = 0; k < 4; ++k) {
            const PParam pp = sp[p0 + k];
            float res = vA[k] * pp.wA + vB[k] * pp.wB + vC[k] * pp.wC + vD[k] * pp.wD;
            out[oRow + (p0 + k) * 32u] = res;
        }
    }
}

extern "C" void kernel_launch(void* const* d_in, const int* in_sizes, int n_in,
                              void* d_out, int out_size)
{
    const float* image = (const float*)d_in[0];
    const float* theta = (const float*)d_in[1];
    float*       out   = (float*)d_out;

    stn_bilinear_kernel<<<8192, 256>>>(image, theta, out);
}

// round 11
// speedup vs baseline: 1.2642x; 1.2642x over previous
#include <cuda_runtime.h>

#define BATCH 32
#define IN_H  128
#define IN_W  512
#define CHAN  32
#define OUT_H 64
#define OUT_W 256

// R6 machinery + 2D output tile per block for L1 tap-dedupe.
// Block = 256 threads, covers 64 points = 16 wx x 4 hy (consecutive in both
// axes -> tap lines overlap between neighboring points in x AND y).
// Phase 1: threads 0..63 compute weights + pixel indices -> smem.
// Phase 2: 8 threads per point (float4 channel group), 2 points per thread.
// Stores via __stcg. 32 regs / 8 CTAs per SM.
// Grid = 16 wx-tiles * 16 hy-tiles * 32 b = 8192 blocks.

struct PParam {
    float    wA, wB, wC, wD;
    unsigned iA, iB, iC, iD;   // pixel index * 8 (float4 units), without cg
};

__global__ void __launch_bounds__(256, 8)
stn_bilinear_kernel(const float* __restrict__ image,
                    const float* __restrict__ theta,
                    float* __restrict__ out)
{
    __shared__ PParam sp[64];

    const unsigned tid = threadIdx.x;
    const unsigned bid = blockIdx.x;
    const unsigned wx_base = (bid & 15u) << 4;       // 16 tiles of 16 wx
    const unsigned r       = bid >> 4;
    const unsigned hy_base = (r & 15u) << 2;         // 16 tiles of 4 hy
    const unsigned b       = r >> 4;                 // 0..31

    // ---- Phase 1: 64 threads compute params for the 16x4 point tile ----
    if (tid < 64u) {
        const unsigned wx = wx_base + (tid & 15u);
        const unsigned hy = hy_base + (tid >> 4);    // 4 consecutive rows

        const float xg = (float)wx * (2.0f / 255.0f) - 1.0f;
        const float yg = (float)hy * (2.0f / 63.0f) - 1.0f;

        // theta[b] 2x3; reference hack: zero row 1 of batch 0, row 0 of batch 1
        const float* th = theta + b * 6u;
        float t00 = __ldg(th + 0), t01 = __ldg(th + 1), t02 = __ldg(th + 2);
        float t10 = __ldg(th + 3), t11 = __ldg(th + 4), t12 = __ldg(th + 5);
        if (b == 0u) { t10 = 0.0f; t11 = 0.0f; t12 = 0.0f; }
        if (b == 1u) { t00 = 0.0f; t01 = 0.0f; t02 = 0.0f; }

        float cx = t00 * xg + t01 * yg + t02;
        float cy = t10 * xg + t11 * yg + t12;

        float x = 0.5f * (cx + 1.0f) * (float)IN_W;   // uses W, not W-1
        float y = 0.5f * (cy + 1.0f) * (float)IN_H;

        int x0 = (int)x;                              // trunc toward zero
        int y0 = (int)y;
        int x1 = x0 + 1;
        int y1 = y0 + 1;
        x0 = min(max(x0, 0), IN_W - 1);               // clip BEFORE weights
        x1 = min(max(x1, 0), IN_W - 1);
        y0 = min(max(y0, 0), IN_H - 1);
        y1 = min(max(y1, 0), IN_H - 1);

        float x0f = (float)x0, x1f = (float)x1;
        float y0f = (float)y0, y1f = (float)y1;

        PParam pp;
        pp.wA = (x1f - x) * (y1f - y);
        pp.wB = (x1f - x) * (y - y0f);
        pp.wC = (x - x0f) * (y1f - y);
        pp.wD = (x - x0f) * (y - y0f);

        const unsigned basePix = b * (unsigned)(IN_H * IN_W);
        const unsigned row0 = basePix + (unsigned)y0 * (unsigned)IN_W;
        const unsigned row1 = basePix + (unsigned)y1 * (unsigned)IN_W;
        pp.iA = (row0 + (unsigned)x0) << 3;
        pp.iB = (row1 + (unsigned)x0) << 3;
        pp.iC = (row0 + (unsigned)x1) << 3;
        pp.iD = (row1 + (unsigned)x1) << 3;

        sp[tid] = pp;
    }
    __syncthreads();

    // ---- Phase 2: 8 threads per point, 2 points per thread ----
    const unsigned cg = tid & 7u;
    const unsigned p0 = tid >> 3;        // 0..31 ; second point = p0 + 32

    const float4* __restrict__ img4 = (const float4*)image;
    float4* __restrict__ out4 = (float4*)out;

    #pragma unroll
    for (int half = 0; half < 2; ++half) {
        const unsigned p  = p0 + (unsigned)half * 32u;
        const PParam pp = sp[p];

        float4 pA = __ldg(img4 + (pp.iA + cg));
        float4 pB = __ldg(img4 + (pp.iB + cg));
        float4 pC = __ldg(img4 + (pp.iC + cg));
        float4 pD = __ldg(img4 + (pp.iD + cg));

        float4 res;
        res.x = pA.x * pp.wA + pB.x * pp.wB + pC.x * pp.wC + pD.x * pp.wD;
        res.y = pA.y * pp.wA + pB.y * pp.wB + pC.y * pp.wC + pD.y * pp.wD;
        res.z = pA.z * pp.wA + pB.z * pp.wB + pC.z * pp.wC + pD.z * pp.wD;
        res.w = pA.w * pp.wA + pB.w * pp.wB + pC.w * pp.wC + pD.w * pp.wD;

        const unsigned wx = wx_base + (p & 15u);
        const unsigned hy = hy_base + (p >> 4);
        const unsigned oIdx = ((b * (unsigned)OUT_H + hy) * (unsigned)OUT_W + wx) * 8u + cg;
        __stcg(&out4[oIdx], res);
    }
}

extern "C" void kernel_launch(void* const* d_in, const int* in_sizes, int n_in,
                              void* d_out, int out_size)
{
    const float* image = (const float*)d_in[0];
    const float* theta = (const float*)d_in[1];
    float*       out   = (float*)d_out;

    stn_bilinear_kernel<<<8192, 256>>>(image, theta, out);
}